// round 3
// baseline (speedup 1.0000x reference)
#include <cuda_runtime.h>
#include <cstdint>

#define NN 100000
#define EE 1200000

// Scratch (all __device__ globals — no allocs)
__device__ float g_agg[NN * 64];      // aggregated messages
__device__ int   g_cnt[NN];           // per-dst degree
__device__ int   g_off[NN + 1];       // CSR offsets
__device__ int   g_cursor[NN];        // fill cursors
__device__ int   g_part[128];         // scan partials
__device__ int   g_ebin[EE];          // edge ids grouped by dst

// ---------------------------------------------------------------------------
// CSR build: histogram -> scan -> reorder
// ---------------------------------------------------------------------------
__global__ void zero_cnt_kernel(int N) {
    int i = blockIdx.x * blockDim.x + threadIdx.x;
    if (i < N) g_cnt[i] = 0;
}

__global__ void hist_kernel(const int* __restrict__ ei, int E) {
    int e = blockIdx.x * blockDim.x + threadIdx.x;
    if (e < E) atomicAdd(&g_cnt[__ldg(ei + E + e)], 1);
}

// Block-wise inclusive scan (1024/block); writes exclusive offsets + block sums
__global__ void __launch_bounds__(1024) scan_a_kernel(int N) {
    __shared__ int sh[1024];
    int i = blockIdx.x * 1024 + threadIdx.x;
    int v = (i < N) ? g_cnt[i] : 0;
    sh[threadIdx.x] = v;
    __syncthreads();
    int x = v;
#pragma unroll
    for (int d = 1; d < 1024; d <<= 1) {
        int t = (threadIdx.x >= d) ? sh[threadIdx.x - d] : 0;
        __syncthreads();
        x += t;
        sh[threadIdx.x] = x;
        __syncthreads();
    }
    if (i < N) g_off[i] = x - v;                 // exclusive within block
    if (threadIdx.x == 1023) g_part[blockIdx.x] = x;  // block total
}

// Scan the (<=128) block partials -> exclusive
__global__ void scan_b_kernel(int nb) {
    __shared__ int sh[128];
    int v = (threadIdx.x < nb) ? g_part[threadIdx.x] : 0;
    sh[threadIdx.x] = v;
    __syncthreads();
    int x = v;
#pragma unroll
    for (int d = 1; d < 128; d <<= 1) {
        int t = (threadIdx.x >= d) ? sh[threadIdx.x - d] : 0;
        __syncthreads();
        x += t;
        sh[threadIdx.x] = x;
        __syncthreads();
    }
    if (threadIdx.x < nb) g_part[threadIdx.x] = x - v;
}

// Add back partials; init cursors; cap offsets
__global__ void scan_c_kernel(int N, int E) {
    int i = blockIdx.x * blockDim.x + threadIdx.x;
    if (i < N) {
        int o = g_off[i] + g_part[i >> 10];
        g_off[i] = o;
        g_cursor[i] = o;
    }
    if (i == 0) g_off[N] = E;
}

__global__ void reorder_kernel(const int* __restrict__ ei, int E) {
    int e = blockIdx.x * blockDim.x + threadIdx.x;
    if (e < E) {
        int d = __ldg(ei + E + e);
        int p = atomicAdd(&g_cursor[d], 1);
        g_ebin[p] = e;
    }
}

// ---------------------------------------------------------------------------
// Gather-reduce: one warp per dst node, no atomics. 2 floats/lane in regs.
// ---------------------------------------------------------------------------
__global__ void __launch_bounds__(256) gather_kernel(
    const float* __restrict__ nf, const float* __restrict__ ef,
    const int* __restrict__ ei, int N) {
    int w = (blockIdx.x * 256 + threadIdx.x) >> 5;
    int lane = threadIdx.x & 31;
    if (w >= N) return;
    int beg = g_off[w], end = g_off[w + 1];
    float a0 = 0.f, a1 = 0.f;
    int j = beg;
    for (; j + 1 < end; j += 2) {
        int e0 = __ldg(g_ebin + j), e1 = __ldg(g_ebin + j + 1);
        int s0 = __ldg(ei + e0), s1 = __ldg(ei + e1);
        float n00 = __ldg(nf + (size_t)s0 * 64 + lane);
        float n01 = __ldg(nf + (size_t)s0 * 64 + 32 + lane);
        float f00 = __ldg(ef + (size_t)e0 * 64 + lane);
        float f01 = __ldg(ef + (size_t)e0 * 64 + 32 + lane);
        float n10 = __ldg(nf + (size_t)s1 * 64 + lane);
        float n11 = __ldg(nf + (size_t)s1 * 64 + 32 + lane);
        float f10 = __ldg(ef + (size_t)e1 * 64 + lane);
        float f11 = __ldg(ef + (size_t)e1 * 64 + 32 + lane);
        a0 += n00 + f00; a1 += n01 + f01;
        a0 += n10 + f10; a1 += n11 + f11;
    }
    if (j < end) {
        int e0 = __ldg(g_ebin + j);
        int s0 = __ldg(ei + e0);
        a0 += __ldg(nf + (size_t)s0 * 64 + lane) + __ldg(ef + (size_t)e0 * 64 + lane);
        a1 += __ldg(nf + (size_t)s0 * 64 + 32 + lane) + __ldg(ef + (size_t)e0 * 64 + 32 + lane);
    }
    g_agg[(size_t)w * 64 + lane] = a0;
    g_agg[(size_t)w * 64 + 32 + lane] = a1;
}

// ---------------------------------------------------------------------------
// Packed f32x2 helpers
// ---------------------------------------------------------------------------
__device__ __forceinline__ unsigned long long fma2(unsigned long long a,
                                                   unsigned long long b,
                                                   unsigned long long c) {
    unsigned long long d;
    asm("fma.rn.f32x2 %0, %1, %2, %3;" : "=l"(d) : "l"(a), "l"(b), "l"(c));
    return d;
}
__device__ __forceinline__ unsigned long long pack2(float x, float y) {
    unsigned long long d;
    asm("mov.b64 %0, {%1, %2};" : "=l"(d) : "f"(x), "f"(y));
    return d;
}
__device__ __forceinline__ void unpack2(unsigned long long v, float& x, float& y) {
    asm("mov.b64 {%0, %1}, %2;" : "=f"(x), "=f"(y) : "l"(v));
}

// ---------------------------------------------------------------------------
// Fused 2-layer MLP as smem-staged register-tiled FFMA2 GEMM (unchanged)
// ---------------------------------------------------------------------------
#define BM 64
#define MLP_THREADS 256
#define AT_STRIDE 68
#define HS_STRIDE 68
#define SM_AT 0
#define SM_W1 (SM_AT + 64 * AT_STRIDE)
#define SM_HS (SM_W1 + 64 * 128)
#define SM_W2 (SM_HS + 128 * HS_STRIDE)
#define SM_FLOATS (SM_W2 + 128 * 64)
#define SMEM_BYTES (SM_FLOATS * 4)

__global__ void __launch_bounds__(MLP_THREADS) mlp_kernel(
    const float* __restrict__ W1, const float* __restrict__ b1,
    const float* __restrict__ W2, const float* __restrict__ b2,
    float* __restrict__ out, int N) {
    extern __shared__ float sm[];
    float* aT  = sm + SM_AT;
    float* W1s = sm + SM_W1;
    float* Hs  = sm + SM_HS;
    float* W2s = sm + SM_W2;
    int tid = threadIdx.x;
    int node0 = blockIdx.x * BM;

#pragma unroll
    for (int i = 0; i < 8; i++) {
        int f = tid + i * 256;
        ((float4*)W1s)[f] = __ldg(((const float4*)W1) + f);
    }
#pragma unroll
    for (int i = 0; i < 8; i++) {
        int f = tid + i * 256;
        ((float4*)W2s)[f] = __ldg(((const float4*)W2) + f);
    }
#pragma unroll
    for (int i = 0; i < 4; i++) {
        int f = tid + i * 256;
        int r = f >> 4;
        int c4 = f & 15;
        int n = node0 + r;
        float4 v = (n < N) ? __ldg(((const float4*)g_agg) + (size_t)n * 16 + c4)
                           : make_float4(0.f, 0.f, 0.f, 0.f);
        int c = c4 * 4;
        aT[(c + 0) * AT_STRIDE + r] = v.x;
        aT[(c + 1) * AT_STRIDE + r] = v.y;
        aT[(c + 2) * AT_STRIDE + r] = v.z;
        aT[(c + 3) * AT_STRIDE + r] = v.w;
    }
    __syncthreads();

    int m0 = (tid & 15) * 4;
    int j0 = (tid >> 4) * 8;

    unsigned long long acc[4][4];
    {
        float4 blo = __ldg((const float4*)(b1 + j0));
        float4 bhi = __ldg((const float4*)(b1 + j0 + 4));
        unsigned long long bj[4] = { pack2(blo.x, blo.y), pack2(blo.z, blo.w),
                                     pack2(bhi.x, bhi.y), pack2(bhi.z, bhi.w) };
#pragma unroll
        for (int m = 0; m < 4; m++)
#pragma unroll
            for (int p = 0; p < 4; p++) acc[m][p] = bj[p];
    }
#pragma unroll 4
    for (int k = 0; k < 64; k++) {
        float4 av = *(const float4*)(aT + k * AT_STRIDE + m0);
        const float4* wp = (const float4*)(W1s + k * 128 + j0);
        float4 w0 = wp[0], w1 = wp[1];
        unsigned long long wv[4] = { pack2(w0.x, w0.y), pack2(w0.z, w0.w),
                                     pack2(w1.x, w1.y), pack2(w1.z, w1.w) };
        unsigned long long am[4] = { pack2(av.x, av.x), pack2(av.y, av.y),
                                     pack2(av.z, av.z), pack2(av.w, av.w) };
#pragma unroll
        for (int m = 0; m < 4; m++)
#pragma unroll
            for (int p = 0; p < 4; p++)
                acc[m][p] = fma2(am[m], wv[p], acc[m][p]);
    }
#pragma unroll
    for (int m = 0; m < 4; m++)
#pragma unroll
        for (int p = 0; p < 4; p++) {
            float x, y; unpack2(acc[m][p], x, y);
            Hs[(j0 + 2 * p + 0) * HS_STRIDE + m0 + m] = fmaxf(x, 0.f);
            Hs[(j0 + 2 * p + 1) * HS_STRIDE + m0 + m] = fmaxf(y, 0.f);
        }
    __syncthreads();

    int j0b = (tid >> 4) * 4;
    unsigned long long acc2[4][2];
    {
        float4 bv = __ldg((const float4*)(b2 + j0b));
        unsigned long long bA = pack2(bv.x, bv.y), bB = pack2(bv.z, bv.w);
#pragma unroll
        for (int m = 0; m < 4; m++) { acc2[m][0] = bA; acc2[m][1] = bB; }
    }
#pragma unroll 4
    for (int k = 0; k < 128; k++) {
        float4 hv = *(const float4*)(Hs + k * HS_STRIDE + m0);
        float4 wv4 = *(const float4*)(W2s + k * 64 + j0b);
        unsigned long long wv[2] = { pack2(wv4.x, wv4.y), pack2(wv4.z, wv4.w) };
        unsigned long long hm[4] = { pack2(hv.x, hv.x), pack2(hv.y, hv.y),
                                     pack2(hv.z, hv.z), pack2(hv.w, hv.w) };
#pragma unroll
        for (int m = 0; m < 4; m++) {
            acc2[m][0] = fma2(hm[m], wv[0], acc2[m][0]);
            acc2[m][1] = fma2(hm[m], wv[1], acc2[m][1]);
        }
    }
#pragma unroll
    for (int m = 0; m < 4; m++) {
        int n = node0 + m0 + m;
        if (n < N) {
            float4 v;
            unpack2(acc2[m][0], v.x, v.y);
            unpack2(acc2[m][1], v.z, v.w);
            *(float4*)(out + (size_t)n * 64 + j0b) = v;
        }
    }
}

// ---------------------------------------------------------------------------
// Launch: CSR build -> gather-reduce -> tiled MLP
// ---------------------------------------------------------------------------
extern "C" void kernel_launch(void* const* d_in, const int* in_sizes, int n_in,
                              void* d_out, int out_size) {
    const float* node_feat = (const float*)d_in[0];
    const float* edge_feat = (const float*)d_in[1];
    const int*   ei        = (const int*)d_in[2];
    const float* W1        = (const float*)d_in[3];
    const float* b1        = (const float*)d_in[4];
    const float* W2        = (const float*)d_in[5];
    const float* b2        = (const float*)d_in[6];
    float* out = (float*)d_out;

    int N = in_sizes[0] / 64;   // 100000
    int E = in_sizes[2] / 2;    // 1200000
    int nb = (N + 1023) / 1024; // scan blocks (98)

    cudaFuncSetAttribute(mlp_kernel, cudaFuncAttributeMaxDynamicSharedMemorySize,
                         SMEM_BYTES);

    zero_cnt_kernel<<<(N + 255) / 256, 256>>>(N);
    hist_kernel<<<(E + 255) / 256, 256>>>(ei, E);
    scan_a_kernel<<<nb, 1024>>>(N);
    scan_b_kernel<<<1, 128>>>(nb);
    scan_c_kernel<<<(N + 255) / 256, 256>>>(N, E);
    reorder_kernel<<<(E + 255) / 256, 256>>>(ei, E);
    gather_kernel<<<(N * 32 + 255) / 256, 256>>>(node_feat, edge_feat, ei, N);
    mlp_kernel<<<(N + BM - 1) / BM, MLP_THREADS, SMEM_BYTES>>>(W1, b1, W2, b2, out, N);
}

// round 4
// speedup vs baseline: 1.1346x; 1.1346x over previous
#include <cuda_runtime.h>
#include <cstdint>

#define NN 100000
#define EE 1200000

// Scratch: aggregated messages per node [N, 64]
__device__ float g_agg[NN * 64];

// ---------------------------------------------------------------------------
// Kernel 0: zero the aggregation buffer
// ---------------------------------------------------------------------------
__global__ void zero_agg_kernel(int n4) {
    int i = blockIdx.x * blockDim.x + threadIdx.x;
    if (i < n4) ((float4*)g_agg)[i] = make_float4(0.f, 0.f, 0.f, 0.f);
}

// ---------------------------------------------------------------------------
// Kernel 1: scatter-add  agg[dst] += node_feat[src] + edge_feat[e]
// (round-2 version: L2-atomic RED.v4, at the LTS structural floor)
// ---------------------------------------------------------------------------
__global__ void scatter_kernel(const float* __restrict__ node_feat,
                               const float* __restrict__ edge_feat,
                               const int* __restrict__ ei, int E) {
    int gid = blockIdx.x * blockDim.x + threadIdx.x;
    if (gid >= E * 16) return;
    int e = gid >> 4;
    int c = gid & 15;
    int s = __ldg(ei + e);
    int d = __ldg(ei + E + e);
    float4 nf = __ldg(((const float4*)node_feat) + s * 16 + c);
    float4 ef = __ldg(((const float4*)edge_feat) + (size_t)e * 16 + c);
    float4 m = make_float4(nf.x + ef.x, nf.y + ef.y, nf.z + ef.z, nf.w + ef.w);
    float* p = g_agg + (size_t)d * 64 + (c << 2);
    asm volatile("red.global.add.v4.f32 [%0], {%1, %2, %3, %4};"
                 :: "l"(p), "f"(m.x), "f"(m.y), "f"(m.z), "f"(m.w)
                 : "memory");
}

// ---------------------------------------------------------------------------
// Packed f32x2 helpers
// ---------------------------------------------------------------------------
__device__ __forceinline__ unsigned long long fma2(unsigned long long a,
                                                   unsigned long long b,
                                                   unsigned long long c) {
    unsigned long long d;
    asm("fma.rn.f32x2 %0, %1, %2, %3;" : "=l"(d) : "l"(a), "l"(b), "l"(c));
    return d;
}
__device__ __forceinline__ unsigned long long pack2(float x, float y) {
    unsigned long long d;
    asm("mov.b64 %0, {%1, %2};" : "=l"(d) : "f"(x), "f"(y));
    return d;
}
__device__ __forceinline__ void unpack2(unsigned long long v, float& x, float& y) {
    asm("mov.b64 {%0, %1}, %2;" : "=f"(x), "=f"(y) : "l"(v));
}

// ---------------------------------------------------------------------------
// Kernel 2: fused MLP. BM=128 nodes/block, 256 threads.
// GEMM1 (A[128x64] @ W1[64x128]): thread tile 8m x 8j, m split in quadrants
//   (m0, m0+64) so half-warp aT loads are contiguous (conflict-free) and all
//   weight loads are half-warp broadcasts.
// GEMM2 (H[128x128] @ W2[128x64]): 128 threads, same 8m x 8j quadrant scheme.
// ---------------------------------------------------------------------------
#define BM 128
#define MLP_THREADS 256
#define AT_S 132    // aT [64][132]
#define HS_S 132    // Hs [128][132]
#define SM_AT 0
#define SM_W1 (SM_AT + 64 * AT_S)
#define SM_HS (SM_W1 + 64 * 128)
#define SM_W2 (SM_HS + 128 * HS_S)
#define SM_FLOATS (SM_W2 + 128 * 64)
#define SMEM_BYTES (SM_FLOATS * 4)

__global__ void __launch_bounds__(MLP_THREADS) mlp_kernel(
    const float* __restrict__ W1, const float* __restrict__ b1,
    const float* __restrict__ W2, const float* __restrict__ b2,
    float* __restrict__ out, int N) {
    extern __shared__ float sm[];
    float* aT  = sm + SM_AT;
    float* W1s = sm + SM_W1;
    float* Hs  = sm + SM_HS;
    float* W2s = sm + SM_W2;
    int tid = threadIdx.x;
    int node0 = blockIdx.x * BM;

    // Stage W1 [64][128], W2 [128][64]
#pragma unroll
    for (int i = 0; i < 8; i++) {
        int f = tid + i * 256;
        ((float4*)W1s)[f] = __ldg(((const float4*)W1) + f);
        ((float4*)W2s)[f] = __ldg(((const float4*)W2) + f);
    }
    // Stage agg tile transposed: aT[k][m] = agg[node0+m][k]  (128 x 64)
#pragma unroll
    for (int i = 0; i < 8; i++) {
        int f = tid + i * 256;          // 0..2047
        int r = f >> 4;                 // node in tile 0..127
        int c4 = f & 15;
        int n = node0 + r;
        float4 v = (n < N) ? __ldg(((const float4*)g_agg) + (size_t)n * 16 + c4)
                           : make_float4(0.f, 0.f, 0.f, 0.f);
        int c = c4 * 4;
        aT[(c + 0) * AT_S + r] = v.x;
        aT[(c + 1) * AT_S + r] = v.y;
        aT[(c + 2) * AT_S + r] = v.z;
        aT[(c + 3) * AT_S + r] = v.w;
    }
    __syncthreads();

    // ---------------- GEMM1: H = relu(A @ W1 + b1) ----------------
    {
        int mg = tid & 15;          // m quadrants: [4mg, 4mg+4) and [64+4mg, ...)
        int jg = tid >> 4;          // j group: [8jg, 8jg+8)  (broadcast loads)
        int m0 = mg * 4;
        int j0 = jg * 8;

        unsigned long long acc[8][4];
        {
            float4 blo = __ldg((const float4*)(b1 + j0));
            float4 bhi = __ldg((const float4*)(b1 + j0 + 4));
            unsigned long long bj[4] = { pack2(blo.x, blo.y), pack2(blo.z, blo.w),
                                         pack2(bhi.x, bhi.y), pack2(bhi.z, bhi.w) };
#pragma unroll
            for (int m = 0; m < 8; m++)
#pragma unroll
                for (int p = 0; p < 4; p++) acc[m][p] = bj[p];
        }
#pragma unroll 4
        for (int k = 0; k < 64; k++) {
            float4 a0 = *(const float4*)(aT + k * AT_S + m0);
            float4 a1 = *(const float4*)(aT + k * AT_S + 64 + m0);
            float4 w0 = *(const float4*)(W1s + k * 128 + j0);
            float4 w1 = *(const float4*)(W1s + k * 128 + j0 + 4);
            unsigned long long wv[4] = { pack2(w0.x, w0.y), pack2(w0.z, w0.w),
                                         pack2(w1.x, w1.y), pack2(w1.z, w1.w) };
            float a[8] = { a0.x, a0.y, a0.z, a0.w, a1.x, a1.y, a1.z, a1.w };
#pragma unroll
            for (int m = 0; m < 8; m++) {
                unsigned long long am = pack2(a[m], a[m]);
#pragma unroll
                for (int p = 0; p < 4; p++)
                    acc[m][p] = fma2(am, wv[p], acc[m][p]);
            }
        }
        // ReLU -> Hs[j][m]; per j-row each half-warp writes contiguous floats
#pragma unroll
        for (int p = 0; p < 4; p++) {
#pragma unroll
            for (int h = 0; h < 2; h++) {   // the two j's inside the pair
                float lo4[4], hi4[4];
#pragma unroll
                for (int m = 0; m < 4; m++) {
                    float x, y;
                    unpack2(acc[m][p], x, y);
                    lo4[m] = fmaxf(h == 0 ? x : y, 0.f);
                    unpack2(acc[4 + m][p], x, y);
                    hi4[m] = fmaxf(h == 0 ? x : y, 0.f);
                }
                int j = j0 + 2 * p + h;
                *(float4*)(Hs + j * HS_S + m0)      = make_float4(lo4[0], lo4[1], lo4[2], lo4[3]);
                *(float4*)(Hs + j * HS_S + 64 + m0) = make_float4(hi4[0], hi4[1], hi4[2], hi4[3]);
            }
        }
    }
    __syncthreads();

    // ---------------- GEMM2: out = H @ W2 + b2  (threads 0..127) ----------------
    if (tid < 128) {
        int mg = tid & 15;
        int jg = tid >> 4;          // 0..7
        int m0 = mg * 4;
        int j0 = jg * 8;

        unsigned long long acc[8][4];
        {
            float4 blo = __ldg((const float4*)(b2 + j0));
            float4 bhi = __ldg((const float4*)(b2 + j0 + 4));
            unsigned long long bj[4] = { pack2(blo.x, blo.y), pack2(blo.z, blo.w),
                                         pack2(bhi.x, bhi.y), pack2(bhi.z, bhi.w) };
#pragma unroll
            for (int m = 0; m < 8; m++)
#pragma unroll
                for (int p = 0; p < 4; p++) acc[m][p] = bj[p];
        }
#pragma unroll 4
        for (int k = 0; k < 128; k++) {
            float4 h0 = *(const float4*)(Hs + k * HS_S + m0);
            float4 h1 = *(const float4*)(Hs + k * HS_S + 64 + m0);
            float4 w0 = *(const float4*)(W2s + k * 64 + j0);
            float4 w1 = *(const float4*)(W2s + k * 64 + j0 + 4);
            unsigned long long wv[4] = { pack2(w0.x, w0.y), pack2(w0.z, w0.w),
                                         pack2(w1.x, w1.y), pack2(w1.z, w1.w) };
            float hvals[8] = { h0.x, h0.y, h0.z, h0.w, h1.x, h1.y, h1.z, h1.w };
#pragma unroll
            for (int m = 0; m < 8; m++) {
                unsigned long long hm = pack2(hvals[m], hvals[m]);
#pragma unroll
                for (int p = 0; p < 4; p++)
                    acc[m][p] = fma2(hm, wv[p], acc[m][p]);
            }
        }
        // Write out: m quadrants (m0.., 64+m0..), j in [j0, j0+8)
#pragma unroll
        for (int m = 0; m < 8; m++) {
            int n = node0 + ((m < 4) ? (m0 + m) : (64 + m0 + m - 4));
            if (n < N) {
                float4 v0, v1;
                unpack2(acc[m][0], v0.x, v0.y);
                unpack2(acc[m][1], v0.z, v0.w);
                unpack2(acc[m][2], v1.x, v1.y);
                unpack2(acc[m][3], v1.z, v1.w);
                *(float4*)(out + (size_t)n * 64 + j0)     = v0;
                *(float4*)(out + (size_t)n * 64 + j0 + 4) = v1;
            }
        }
    }
}

// ---------------------------------------------------------------------------
// Launch: zero -> atomic scatter -> tiled MLP
// ---------------------------------------------------------------------------
extern "C" void kernel_launch(void* const* d_in, const int* in_sizes, int n_in,
                              void* d_out, int out_size) {
    const float* node_feat = (const float*)d_in[0];
    const float* edge_feat = (const float*)d_in[1];
    const int*   ei        = (const int*)d_in[2];
    const float* W1        = (const float*)d_in[3];
    const float* b1        = (const float*)d_in[4];
    const float* W2        = (const float*)d_in[5];
    const float* b2        = (const float*)d_in[6];
    float* out = (float*)d_out;

    int N = in_sizes[0] / 64;   // 100000
    int E = in_sizes[2] / 2;    // 1200000

    cudaFuncSetAttribute(mlp_kernel, cudaFuncAttributeMaxDynamicSharedMemorySize,
                         SMEM_BYTES);

    int n4 = N * 16;
    zero_agg_kernel<<<(n4 + 255) / 256, 256>>>(n4);
    scatter_kernel<<<(E * 16 + 255) / 256, 256>>>(node_feat, edge_feat, ei, E);
    mlp_kernel<<<(N + BM - 1) / BM, MLP_THREADS, SMEM_BYTES>>>(W1, b1, W2, b2, out, N);
}

// round 5
// speedup vs baseline: 1.1937x; 1.0521x over previous
#include <cuda_runtime.h>
#include <cstdint>

#define NN 100000
#define EE 1200000

// Scratch: aggregated messages per node [N, 64]
__device__ float g_agg[NN * 64];

// ---------------------------------------------------------------------------
// Kernel 0: zero the aggregation buffer
// ---------------------------------------------------------------------------
__global__ void zero_agg_kernel(int n4) {
    int i = blockIdx.x * blockDim.x + threadIdx.x;
    if (i < n4) ((float4*)g_agg)[i] = make_float4(0.f, 0.f, 0.f, 0.f);
}

// ---------------------------------------------------------------------------
// Kernel 1: scatter-add  agg[dst] += node_feat[src] + edge_feat[e]
// (unchanged: L2-atomic RED.v4, at the LTS traffic floor)
// ---------------------------------------------------------------------------
__global__ void scatter_kernel(const float* __restrict__ node_feat,
                               const float* __restrict__ edge_feat,
                               const int* __restrict__ ei, int E) {
    int gid = blockIdx.x * blockDim.x + threadIdx.x;
    if (gid >= E * 16) return;
    int e = gid >> 4;
    int c = gid & 15;
    int s = __ldg(ei + e);
    int d = __ldg(ei + E + e);
    float4 nf = __ldg(((const float4*)node_feat) + s * 16 + c);
    float4 ef = __ldg(((const float4*)edge_feat) + (size_t)e * 16 + c);
    float4 m = make_float4(nf.x + ef.x, nf.y + ef.y, nf.z + ef.z, nf.w + ef.w);
    float* p = g_agg + (size_t)d * 64 + (c << 2);
    asm volatile("red.global.add.v4.f32 [%0], {%1, %2, %3, %4};"
                 :: "l"(p), "f"(m.x), "f"(m.y), "f"(m.z), "f"(m.w)
                 : "memory");
}

// ---------------------------------------------------------------------------
// Packed f32x2 helpers
// ---------------------------------------------------------------------------
__device__ __forceinline__ unsigned long long fma2(unsigned long long a,
                                                   unsigned long long b,
                                                   unsigned long long c) {
    unsigned long long d;
    asm("fma.rn.f32x2 %0, %1, %2, %3;" : "=l"(d) : "l"(a), "l"(b), "l"(c));
    return d;
}
__device__ __forceinline__ unsigned long long pack2(float x, float y) {
    unsigned long long d;
    asm("mov.b64 %0, {%1, %2};" : "=l"(d) : "f"(x), "f"(y));
    return d;
}
__device__ __forceinline__ void unpack2(unsigned long long v, float& x, float& y) {
    asm("mov.b64 {%0, %1}, %2;" : "=f"(x), "=f"(y) : "l"(v));
}

// ---------------------------------------------------------------------------
// Kernel 2: fused MLP. BM=128 nodes/block, 256 threads, 2 blocks/SM.
// Smem layout (floats):
//   phase A: [0..8192) W1s, [8192..16640) aT      (region0 = 16896 padded)
//   phase B: [0..16896) Hs[128][132]              (aliases W1s+aT)
//   always:  [16896..25088) W2s
// GEMM1: 8m x 8j per thread (m quadrants). GEMM2: all 256 threads, 4m x 8j.
// ---------------------------------------------------------------------------
#define BM 128
#define MLP_THREADS 256
#define AT_S 132
#define HS_S 132
#define SM_W1 0
#define SM_AT 8192
#define SM_HS 0
#define SM_W2 16896
#define SM_FLOATS (SM_W2 + 128 * 64)
#define SMEM_BYTES (SM_FLOATS * 4)

__global__ void __launch_bounds__(MLP_THREADS, 2) mlp_kernel(
    const float* __restrict__ W1, const float* __restrict__ b1,
    const float* __restrict__ W2, const float* __restrict__ b2,
    float* __restrict__ out, int N) {
    extern __shared__ float sm[];
    float* W1s = sm + SM_W1;
    float* aT  = sm + SM_AT;
    float* Hs  = sm + SM_HS;
    float* W2s = sm + SM_W2;
    int tid = threadIdx.x;
    int node0 = blockIdx.x * BM;

    // Stage W1 [64][128], W2 [128][64]
#pragma unroll
    for (int i = 0; i < 8; i++) {
        int f = tid + i * 256;
        ((float4*)W1s)[f] = __ldg(((const float4*)W1) + f);
        ((float4*)W2s)[f] = __ldg(((const float4*)W2) + f);
    }
    // Stage agg tile transposed: aT[k][m] = agg[node0+m][k]  (64 x 128)
#pragma unroll
    for (int i = 0; i < 8; i++) {
        int f = tid + i * 256;          // 0..2047
        int r = f >> 4;                 // node in tile 0..127
        int c4 = f & 15;
        int n = node0 + r;
        float4 v = (n < N) ? __ldg(((const float4*)g_agg) + (size_t)n * 16 + c4)
                           : make_float4(0.f, 0.f, 0.f, 0.f);
        int c = c4 * 4;
        aT[(c + 0) * AT_S + r] = v.x;
        aT[(c + 1) * AT_S + r] = v.y;
        aT[(c + 2) * AT_S + r] = v.z;
        aT[(c + 3) * AT_S + r] = v.w;
    }
    __syncthreads();

    // ---------------- GEMM1: H = relu(A @ W1 + b1) ----------------
    int mg = tid & 15;
    int jg = tid >> 4;
    int m0 = mg * 4;
    int j0 = jg * 8;

    unsigned long long acc[8][4];
    {
        float4 blo = __ldg((const float4*)(b1 + j0));
        float4 bhi = __ldg((const float4*)(b1 + j0 + 4));
        unsigned long long bj[4] = { pack2(blo.x, blo.y), pack2(blo.z, blo.w),
                                     pack2(bhi.x, bhi.y), pack2(bhi.z, bhi.w) };
#pragma unroll
        for (int m = 0; m < 8; m++)
#pragma unroll
            for (int p = 0; p < 4; p++) acc[m][p] = bj[p];
    }
#pragma unroll 4
    for (int k = 0; k < 64; k++) {
        float4 a0 = *(const float4*)(aT + k * AT_S + m0);
        float4 a1 = *(const float4*)(aT + k * AT_S + 64 + m0);
        float4 w0 = *(const float4*)(W1s + k * 128 + j0);
        float4 w1 = *(const float4*)(W1s + k * 128 + j0 + 4);
        unsigned long long wv[4] = { pack2(w0.x, w0.y), pack2(w0.z, w0.w),
                                     pack2(w1.x, w1.y), pack2(w1.z, w1.w) };
        float a[8] = { a0.x, a0.y, a0.z, a0.w, a1.x, a1.y, a1.z, a1.w };
#pragma unroll
        for (int m = 0; m < 8; m++) {
            unsigned long long am = pack2(a[m], a[m]);
#pragma unroll
            for (int p = 0; p < 4; p++)
                acc[m][p] = fma2(am, wv[p], acc[m][p]);
        }
    }
    __syncthreads();    // all reads of aT/W1s done -> safe to overwrite with Hs

    // ReLU -> Hs[j][m]
#pragma unroll
    for (int p = 0; p < 4; p++) {
#pragma unroll
        for (int h = 0; h < 2; h++) {
            float lo4[4], hi4[4];
#pragma unroll
            for (int m = 0; m < 4; m++) {
                float x, y;
                unpack2(acc[m][p], x, y);
                lo4[m] = fmaxf(h == 0 ? x : y, 0.f);
                unpack2(acc[4 + m][p], x, y);
                hi4[m] = fmaxf(h == 0 ? x : y, 0.f);
            }
            int j = j0 + 2 * p + h;
            *(float4*)(Hs + j * HS_S + m0)      = make_float4(lo4[0], lo4[1], lo4[2], lo4[3]);
            *(float4*)(Hs + j * HS_S + 64 + m0) = make_float4(hi4[0], hi4[1], hi4[2], hi4[3]);
        }
    }
    __syncthreads();

    // ---------------- GEMM2: out = H @ W2 + b2  (all 256 threads) ----------------
    {
        int mg2 = tid & 31;         // 32 m-groups of 4 -> covers 128 nodes
        int jg2 = tid >> 5;         // 8 j-groups of 8
        int m02 = mg2 * 4;
        int j02 = jg2 * 8;

        unsigned long long acc2[4][4];
        {
            float4 blo = __ldg((const float4*)(b2 + j02));
            float4 bhi = __ldg((const float4*)(b2 + j02 + 4));
            unsigned long long bj[4] = { pack2(blo.x, blo.y), pack2(blo.z, blo.w),
                                         pack2(bhi.x, bhi.y), pack2(bhi.z, bhi.w) };
#pragma unroll
            for (int m = 0; m < 4; m++)
#pragma unroll
                for (int p = 0; p < 4; p++) acc2[m][p] = bj[p];
        }
#pragma unroll 4
        for (int k = 0; k < 128; k++) {
            float4 hv = *(const float4*)(Hs + k * HS_S + m02);
            float4 w0 = *(const float4*)(W2s + k * 64 + j02);
            float4 w1 = *(const float4*)(W2s + k * 64 + j02 + 4);
            unsigned long long wv[4] = { pack2(w0.x, w0.y), pack2(w0.z, w0.w),
                                         pack2(w1.x, w1.y), pack2(w1.z, w1.w) };
            float h4[4] = { hv.x, hv.y, hv.z, hv.w };
#pragma unroll
            for (int m = 0; m < 4; m++) {
                unsigned long long hm = pack2(h4[m], h4[m]);
#pragma unroll
                for (int p = 0; p < 4; p++)
                    acc2[m][p] = fma2(hm, wv[p], acc2[m][p]);
            }
        }
#pragma unroll
        for (int m = 0; m < 4; m++) {
            int n = node0 + m02 + m;
            if (n < N) {
                float4 v0, v1;
                unpack2(acc2[m][0], v0.x, v0.y);
                unpack2(acc2[m][1], v0.z, v0.w);
                unpack2(acc2[m][2], v1.x, v1.y);
                unpack2(acc2[m][3], v1.z, v1.w);
                *(float4*)(out + (size_t)n * 64 + j02)     = v0;
                *(float4*)(out + (size_t)n * 64 + j02 + 4) = v1;
            }
        }
    }
}

// ---------------------------------------------------------------------------
// Launch: zero -> atomic scatter -> tiled MLP
// ---------------------------------------------------------------------------
extern "C" void kernel_launch(void* const* d_in, const int* in_sizes, int n_in,
                              void* d_out, int out_size) {
    const float* node_feat = (const float*)d_in[0];
    const float* edge_feat = (const float*)d_in[1];
    const int*   ei        = (const int*)d_in[2];
    const float* W1        = (const float*)d_in[3];
    const float* b1        = (const float*)d_in[4];
    const float* W2        = (const float*)d_in[5];
    const float* b2        = (const float*)d_in[6];
    float* out = (float*)d_out;

    int N = in_sizes[0] / 64;   // 100000
    int E = in_sizes[2] / 2;    // 1200000

    cudaFuncSetAttribute(mlp_kernel, cudaFuncAttributeMaxDynamicSharedMemorySize,
                         SMEM_BYTES);

    int n4 = N * 16;
    zero_agg_kernel<<<(n4 + 255) / 256, 256>>>(n4);
    scatter_kernel<<<(E * 16 + 255) / 256, 256>>>(node_feat, edge_feat, ei, E);
    mlp_kernel<<<(N + BM - 1) / BM, MLP_THREADS, SMEM_BYTES>>>(W1, b1, W2, b2, out, N);
}